// round 10
// baseline (speedup 1.0000x reference)
#include <cuda_runtime.h>
#include <math.h>

#define L2L   2
#define HID   512
#define TMAX  20
#define VOC   10000
#define BATCH 32
#define SPOS  49
#define VPAD  10112   // 79*128 (must equal proj GEMM grid.x * 128!)
#define PSL   4       // proj split-K slices

// ---------------- device scratch (static globals: allocation-free) ----------------
__device__ float g_WihT[L2L][HID][4*HID];      // [l][k][n]
__device__ float g_WhhT[L2L][HID][4*HID];
__device__ float g_WqT[HID][HID];              // [k][n]
__device__ float g_hattWT[2*HID][HID];         // [k][n]
__device__ float g_projWT[HID][VPAD];          // [k][v] zero-padded
__device__ float g_keys[BATCH][SPOS][HID];     // tanh(chan@Wk^T+bk), [b][s][d]
__device__ float g_vals[BATCH][SPOS][HID];     // tanh(chan@Wv^T+bv), [b][s][d]
__device__ float g_h[L2L*BATCH*HID];
__device__ float g_c[L2L*BATCH*HID];
__device__ float g_emb[BATCH*HID];
__device__ float g_attn[L2L*BATCH*HID];
__device__ float g_Pg[8][BATCH][4*HID];        // lstm gate partials
__device__ float g_Pp[PSL][BATCH][VPAD];       // projection partials
__device__ float g_Pq[8][L2L*BATCH][HID];      // q partials
__device__ float g_Ph[8][L2L*BATCH][HID];      // hatt partials
__device__ float g_tmp[TMAX][BATCH][VOC];      // logits per t (coalesced layout)

// ---------------- f32x2 packed FMA helpers (Blackwell) ----------------
__device__ __forceinline__ void fma2(unsigned long long &a, unsigned long long x, unsigned long long w){
    asm("fma.rn.f32x2 %0, %1, %2, %0;" : "+l"(a) : "l"(x), "l"(w));
}
__device__ __forceinline__ unsigned long long pack2(float w){
    unsigned long long r;
    asm("mov.b64 %0, {%1, %1};" : "=l"(r) : "f"(w));
    return r;
}

// ---------------- generic transpose with zero-pad:  WT[k][n] = W[n][k] ----------------
__global__ void transpose_pad(const float* __restrict__ W, float* __restrict__ WT,
                              int N, int K, int Npad){
    __shared__ float t[32][33];
    int n0 = blockIdx.x * 32, k0 = blockIdx.y * 32;
    int tx = threadIdx.x, ty = threadIdx.y;
    int n = n0 + ty, k = k0 + tx;
    float v = 0.f;
    if (n < N && k < K) v = W[(size_t)n * K + k];
    t[ty][tx] = v;
    __syncthreads();
    int kk = k0 + ty, nn = n0 + tx;
    if (kk < K && nn < Npad) WT[(size_t)kk * Npad + nn] = t[tx][ty];
}

// ---------------- keys/values precompute ----------------
__global__ void precompute_kv(const float* __restrict__ img, const float* __restrict__ Wk,
                              const float* __restrict__ bk, const float* __restrict__ Wv,
                              const float* __restrict__ bv){
    __shared__ float wk_s[SPOS][SPOS], wv_s[SPOS][SPOS];
    __shared__ float bk_s[SPOS], bv_s[SPOS];
    int tid = threadIdx.x;
    for (int i = tid; i < SPOS*SPOS; i += 128){ wk_s[i/SPOS][i%SPOS] = Wk[i]; wv_s[i/SPOS][i%SPOS] = Wv[i]; }
    if (tid < SPOS){ bk_s[tid] = bk[tid]; bv_s[tid] = bv[tid]; }
    __syncthreads();
    int b = blockIdx.x;
    int d = blockIdx.y * 128 + tid;
    float ch[SPOS];
    const float* cp = img + ((size_t)b * HID + d) * SPOS;
    #pragma unroll
    for (int s = 0; s < SPOS; s++) ch[s] = cp[s];
    for (int s = 0; s < SPOS; s++){
        float ak = bk_s[s], av = bv_s[s];
        #pragma unroll
        for (int sp = 0; sp < SPOS; sp++){ ak += ch[sp] * wk_s[s][sp]; av += ch[sp] * wv_s[s][sp]; }
        g_keys[b][s][d] = tanhf(ak);
        g_vals[b][s][d] = tanhf(av);
    }
}

// ---------------- state init: h=c=pooled (both layers), emb = embed[sos] ----------------
__global__ void init_state(const float* __restrict__ pooled, const float* __restrict__ embed,
                           const int* __restrict__ sos){
    int idx = blockIdx.x * blockDim.x + threadIdx.x;
    if (idx < L2L * BATCH * HID){
        float p = pooled[idx % (BATCH * HID)];
        g_h[idx] = p; g_c[idx] = p;
    }
    if (idx < BATCH * HID){
        g_emb[idx] = embed[(size_t)(*sos) * HID + (idx % HID)];
    }
}

// ---------------- batched-B GEMM with split-K and dual X sources ----------------
// Yp[s][b][n] = sum_{k in slice s} Xsrc[b][k] * WT[k][n]
// slices 0..NS1-1 use (X1, WT1), NS1..gridDim.y-1 use (X2, WT2). All X rows stride HID.
// REQUIREMENT: gridDim.x * 128 == N exactly (no bounds checks).
template<int BEFF>
__global__ __launch_bounds__(128)
void gemm_bk(const float* __restrict__ X1, const float* __restrict__ X2,
             const float* __restrict__ WT1, const float* __restrict__ WT2,
             float* __restrict__ Yp, int N, int NS1, int KC){
    __shared__ __align__(16) float Xs[64][BEFF + 2];
    int tid = threadIdx.x;
    int n = blockIdx.x * 128 + tid;
    int s = blockIdx.y;
    const float* X; const float* WT; int koff;
    if (s < NS1){ X = X1; WT = WT1; koff = s * KC; }
    else        { X = X2; WT = WT2; koff = (s - NS1) * KC; }

    unsigned long long acc[BEFF/2];
    #pragma unroll
    for (int i = 0; i < BEFF/2; i++) acc[i] = 0ULL;

    for (int kc0 = 0; kc0 < KC; kc0 += 64){
        __syncthreads();
        // stage X[b][koff+kc0 .. +64) transposed into SMEM
        for (int i = tid; i < 16 * BEFF; i += 128){
            int b = i / 16, kq = i % 16;
            float4 v = *reinterpret_cast<const float4*>(X + (size_t)b * HID + koff + kc0 + kq * 4);
            Xs[kq*4+0][b] = v.x; Xs[kq*4+1][b] = v.y; Xs[kq*4+2][b] = v.z; Xs[kq*4+3][b] = v.w;
        }
        __syncthreads();
        const float* wp = WT + (size_t)(koff + kc0) * N + n;
        #pragma unroll 8
        for (int k = 0; k < 64; k++){
            unsigned long long w2 = pack2(wp[(size_t)k * N]);
            const unsigned long long* xr = reinterpret_cast<const unsigned long long*>(&Xs[k][0]);
            #pragma unroll
            for (int bb = 0; bb < BEFF/2; bb++) fma2(acc[bb], xr[bb], w2);
        }
    }
    const float2* accf = reinterpret_cast<const float2*>(acc);
    #pragma unroll
    for (int bb = 0; bb < BEFF/2; bb++){
        Yp[((size_t)s * BEFF + 2*bb    ) * N + n] = accf[bb].x;
        Yp[((size_t)s * BEFF + 2*bb + 1) * N + n] = accf[bb].y;
    }
}

// ---------------- LSTM gate activation: reduce 8 partials + biases, update h,c ----------------
__global__ void lstm_act(int l, const float* __restrict__ bih, const float* __restrict__ bhh){
    int b = blockIdx.x, j = threadIdx.x;   // block 512
    int bo = l * 4 * HID;
    float gi = bih[bo + j]           + bhh[bo + j];
    float gf = bih[bo + HID + j]     + bhh[bo + HID + j];
    float gg = bih[bo + 2*HID + j]   + bhh[bo + 2*HID + j];
    float go = bih[bo + 3*HID + j]   + bhh[bo + 3*HID + j];
    #pragma unroll
    for (int s = 0; s < 8; s++){
        const float* p = &g_Pg[s][b][0];
        gi += p[j]; gf += p[HID + j]; gg += p[2*HID + j]; go += p[3*HID + j];
    }
    int idx = (l * BATCH + b) * HID + j;
    float cold = g_c[idx];
    float si = 1.f / (1.f + expf(-gi));
    float sf = 1.f / (1.f + expf(-gf));
    float so = 1.f / (1.f + expf(-go));
    float c2 = sf * cold + si * tanhf(gg);
    g_c[idx] = c2;
    g_h[idx] = so * tanhf(c2);
}

// ---------------- logits: reduce proj partials + bias, store slice t, argmax -> next emb ----------------
__global__ void logits_argmax(const float* __restrict__ projb, const float* __restrict__ embed,
                              int tslot, int do_argmax){
    __shared__ float sv[1024];
    __shared__ int   si[1024];
    __shared__ int   stok;
    int b = blockIdx.x, tid = threadIdx.x;
    float best = -INFINITY; int bi = 0;
    #pragma unroll
    for (int it = 0; it < 10; it++){
        int v = it * 1024 + tid;
        if (v < VOC){
            float val = projb[v];
            #pragma unroll
            for (int s = 0; s < PSL; s++) val += g_Pp[s][b][v];
            g_tmp[tslot][b][v] = val;
            if (val > best){ best = val; bi = v; }
        }
    }
    sv[tid] = best; si[tid] = bi;
    __syncthreads();
    for (int off = 512; off > 0; off >>= 1){
        if (tid < off){
            float ov = sv[tid + off]; int oi = si[tid + off];
            if (ov > sv[tid] || (ov == sv[tid] && oi < si[tid])){ sv[tid] = ov; si[tid] = oi; }
        }
        __syncthreads();
    }
    if (do_argmax){
        if (tid == 0) stok = si[0];
        __syncthreads();
        if (tid < HID) g_emb[b * HID + tid] = embed[(size_t)stok * HID + tid];
    }
}

// ---------------- fused attention: q=tanh(red(Pq)+bq), scores, softmax, attn ----------------
__global__ void attention(const float* __restrict__ bq){
    __shared__ float q_s[HID];
    __shared__ float sc[64];
    int lb = blockIdx.x;          // l*32 + b
    int b = lb & 31;
    int tid = threadIdx.x;        // 256
    for (int j = tid; j < HID; j += 256){
        float a = bq[j];
        #pragma unroll
        for (int s = 0; s < 8; s++) a += g_Pq[s][lb][j];
        q_s[j] = tanhf(a);
    }
    __syncthreads();
    int warp = tid >> 5, lane = tid & 31;
    for (int s = warp; s < SPOS; s += 8){
        const float* kp = &g_keys[b][s][0];
        float d = 0.f;
        #pragma unroll
        for (int k = lane; k < HID; k += 32) d += q_s[k] * kp[k];
        #pragma unroll
        for (int o = 16; o > 0; o >>= 1) d += __shfl_xor_sync(0xffffffff, d, o);
        if (lane == 0) sc[s] = d * (1.f / 7.f);
    }
    __syncthreads();
    if (tid < 32){
        float m = -INFINITY;
        for (int s = tid; s < SPOS; s += 32) m = fmaxf(m, sc[s]);
        #pragma unroll
        for (int o = 16; o > 0; o >>= 1) m = fmaxf(m, __shfl_xor_sync(0xffffffff, m, o));
        float sum = 0.f;
        for (int s = tid; s < SPOS; s += 32){ float e = expf(sc[s] - m); sc[s] = e; sum += e; }
        #pragma unroll
        for (int o = 16; o > 0; o >>= 1) sum += __shfl_xor_sync(0xffffffff, sum, o);
        float inv = 1.f / sum;
        for (int s = tid; s < SPOS; s += 32) sc[s] *= inv;
    }
    __syncthreads();
    for (int d = tid; d < HID; d += 256){
        float a = 0.f;
        #pragma unroll
        for (int s = 0; s < SPOS; s++) a += sc[s] * g_vals[b][s][d];
        g_attn[lb * HID + d] = a;
    }
}

// ---------------- hatt activation: h = tanh(red(Ph) + hattb) ----------------
__global__ void hatt_act(const float* __restrict__ hattb){
    int lb = blockIdx.x, j = threadIdx.x;   // block 512
    float a = hattb[j];
    #pragma unroll
    for (int s = 0; s < 8; s++) a += g_Ph[s][lb][j];
    g_h[lb * HID + j] = tanhf(a);
}

// ---------------- final transpose: tmp[t][b][v] -> out[b][v][t] ----------------
__global__ void final_transpose(float* __restrict__ out){
    int id = blockIdx.x * 256 + threadIdx.x;
    if (id >= BATCH * VOC) return;
    int b = id / VOC, v = id % VOC;
    float r[TMAX];
    #pragma unroll
    for (int t = 0; t < TMAX; t++) r[t] = g_tmp[t][b][v];
    float4* o4 = reinterpret_cast<float4*>(out + ((size_t)b * VOC + v) * TMAX);
    #pragma unroll
    for (int i = 0; i < 5; i++) o4[i] = reinterpret_cast<float4*>(r)[i];
}

// ---------------- host ----------------
static float* symaddr(const void* sym){
    void* p = nullptr;
    cudaGetSymbolAddress(&p, sym);
    return (float*)p;
}

extern "C" void kernel_launch(void* const* d_in, const int* in_sizes, int n_in,
                              void* d_out, int out_size){
    const float* img    = (const float*)d_in[0];
    const float* pooled = (const float*)d_in[1];
    const float* embed  = (const float*)d_in[2];
    const float* Wq     = (const float*)d_in[3];
    const float* bq     = (const float*)d_in[4];
    const float* Wk     = (const float*)d_in[5];
    const float* bk     = (const float*)d_in[6];
    const float* Wv     = (const float*)d_in[7];
    const float* bv     = (const float*)d_in[8];
    const float* Wih    = (const float*)d_in[9];
    const float* Whh    = (const float*)d_in[10];
    const float* bih    = (const float*)d_in[11];
    const float* bhh    = (const float*)d_in[12];
    const float* projW  = (const float*)d_in[13];
    const float* projb  = (const float*)d_in[14];
    const float* hattW  = (const float*)d_in[15];
    const float* hattb  = (const float*)d_in[16];
    const int*   sos    = (const int*)d_in[17];

    float* WihT   = symaddr(g_WihT);
    float* WhhT   = symaddr(g_WhhT);
    float* WqT    = symaddr(g_WqT);
    float* hattWT = symaddr(g_hattWT);
    float* projWT = symaddr(g_projWT);
    float* Pg     = symaddr(g_Pg);
    float* Pp     = symaddr(g_Pp);
    float* Pq     = symaddr(g_Pq);
    float* Ph     = symaddr(g_Ph);
    float* hbuf   = symaddr(g_h);
    float* embb   = symaddr(g_emb);
    float* attnb  = symaddr(g_attn);

    dim3 tb(32, 32);
    // weight transposes (every call; deterministic)
    transpose_pad<<<dim3(16, 16), tb>>>(Wq,    WqT,    HID,  HID,   HID);
    transpose_pad<<<dim3(16, 32), tb>>>(hattW, hattWT, HID,  2*HID, HID);
    // 316*32 = 10112 = VPAD exactly: pad columns written as zeros
    transpose_pad<<<dim3(316,16), tb>>>(projW, projWT, VOC,  HID,   VPAD);
    for (int l = 0; l < L2L; l++){
        transpose_pad<<<dim3(64, 16), tb>>>(Wih + (size_t)l*4*HID*HID, WihT + (size_t)l*HID*4*HID, 4*HID, HID, 4*HID);
        transpose_pad<<<dim3(64, 16), tb>>>(Whh + (size_t)l*4*HID*HID, WhhT + (size_t)l*HID*4*HID, 4*HID, HID, 4*HID);
    }

    precompute_kv<<<dim3(BATCH, 4), 128>>>(img, Wk, bk, Wv, bv);
    init_state<<<128, 256>>>(pooled, embed, sos);

    // t=0 output slice: emb0 @ projW^T + projb (no argmax)
    gemm_bk<32><<<dim3(79, PSL), 128>>>(embb, embb, projWT, projWT, Pp, VPAD, PSL, HID/PSL);
    logits_argmax<<<BATCH, 1024>>>(projb, embed, 0, 0);

    float* h0 = hbuf;
    float* h1 = hbuf + BATCH * HID;

    for (int t = 0; t < TMAX - 1; t++){
        // LSTM layer 0: x = emb, h = h0
        gemm_bk<32><<<dim3(16, 8), 128>>>(embb, h0, WihT, WhhT, Pg, 4*HID, 4, 128);
        lstm_act<<<BATCH, HID>>>(0, bih, bhh);
        // LSTM layer 1: x = h0, h = h1
        gemm_bk<32><<<dim3(16, 8), 128>>>(h0, h1, WihT + (size_t)HID*4*HID, WhhT + (size_t)HID*4*HID, Pg, 4*HID, 4, 128);
        lstm_act<<<BATCH, HID>>>(1, bih, bhh);
        // projection of top-layer output -> slice t+1 + greedy next embedding
        gemm_bk<32><<<dim3(79, PSL), 128>>>(h1, h1, projWT, projWT, Pp, VPAD, PSL, HID/PSL);
        logits_argmax<<<BATCH, 1024>>>(projb, embed, t + 1, 1);
        // cross-attention gated hidden update
        gemm_bk<64><<<dim3(4, 8), 128>>>(hbuf, hbuf, WqT, WqT, Pq, HID, 8, 64);
        attention<<<L2L * BATCH, 256>>>(bq);
        gemm_bk<64><<<dim3(4, 8), 128>>>(attnb, hbuf, hattWT, hattWT + (size_t)HID*HID, Ph, HID, 4, 128);
        hatt_act<<<L2L * BATCH, HID>>>(hattb);
    }

    final_transpose<<<(BATCH * VOC + 255) / 256, 256>>>((float*)d_out);
}

// round 14
// speedup vs baseline: 1.2905x; 1.2905x over previous
#include <cuda_runtime.h>
#include <math.h>

#define L2L   2
#define HID   512
#define TMAX  20
#define VOC   10000
#define BATCH 32
#define SPOS  49
#define VPAD  10112   // 1264*8
#define NB    148     // persistent blocks (<= SM count 152)
#define NT    256     // threads per block (8 warps)
#define GW    (NB*8)  // 1184 global warps

// ---------------- device scratch (static globals: allocation-free) ----------------
__device__ float g_WihT[L2L][HID][4*HID];      // [l][k][n]
__device__ float g_WhhT[L2L][HID][4*HID];
__device__ float g_WqT[HID][HID];              // [k][n]
__device__ float g_hattWT[2*HID][HID];         // [k][n]
__device__ float g_projWT[HID][VPAD];          // [k][v] zero-padded
__device__ float g_keys[BATCH][SPOS][HID];
__device__ float g_vals[BATCH][SPOS][HID];
__device__ float g_h[L2L*BATCH*HID];
__device__ float g_c[L2L*BATCH*HID];
__device__ float g_emb[BATCH*HID];
__device__ float g_attn[L2L*BATCH*HID];
__device__ float g_Pg[16][BATCH][4*HID];       // lstm gate partials (16 k-slices)
__device__ float g_Pp[3][BATCH][VPAD];         // proj partials (3 k-slices)
__device__ float g_Pq[4][L2L*BATCH][HID];      // q partials
__device__ float g_Ph[16][L2L*BATCH][HID];     // hatt partials
__device__ float g_tmp[TMAX][BATCH][VOC];      // logits per t
__device__ float g_amv[BATCH][40];             // per-chunk argmax values
__device__ int   g_ami[BATCH][40];             // per-chunk argmax indices
__device__ unsigned g_bar;                     // packed barrier: count low16, gen high16

// ---------------- f32x2 packed FMA helpers ----------------
__device__ __forceinline__ void fma2(unsigned long long &a, unsigned long long x, unsigned long long w){
    asm("fma.rn.f32x2 %0, %1, %2, %0;" : "+l"(a) : "l"(x), "l"(w));
}
__device__ __forceinline__ unsigned long long pack2(float w){
    unsigned long long r;
    asm("mov.b64 %0, {%1, %1};" : "=l"(r) : "f"(w));
    return r;
}

// ---------------- grid-wide barrier (single packed atomic; race-free gen) ----------------
__device__ __forceinline__ void gridbar(){
    __syncthreads();
    if (threadIdx.x == 0){
        __threadfence();
        unsigned ret = atomicAdd(&g_bar, 1u);
        unsigned gen = ret >> 16;
        if ((ret & 0xFFFFu) == NB - 1u){
            atomicAdd(&g_bar, 0x10000u - NB);   // reset count, bump gen atomically
        } else {
            while (((*(volatile unsigned*)&g_bar) >> 16) == gen){ }
        }
        __threadfence();
    }
    __syncthreads();
}

// ---------------- GEMM thread-unit: 8 cols x 4 rows, K-slice of KC ----------------
// P[(r0+j)*ldo + n0 + c] += over k: X[(r0+j)*HID + koff + k] * WTs[k*ldw + n0 + c]
__device__ __forceinline__ void gemm_unit(const float* __restrict__ X, int koff,
        const float* __restrict__ WTs, int KC, int ldw,
        float* __restrict__ P, int ldo, int n0, int r0){
    unsigned long long acc[4][4];
    #pragma unroll
    for (int c = 0; c < 4; c++)
        #pragma unroll
        for (int j = 0; j < 4; j++) acc[c][j] = 0ULL;
    for (int k4 = 0; k4 < KC; k4 += 4){
        float4 xv[4];
        #pragma unroll
        for (int j = 0; j < 4; j++)
            xv[j] = *reinterpret_cast<const float4*>(X + (size_t)(r0+j)*HID + koff + k4);
        #pragma unroll
        for (int kk = 0; kk < 4; kk++){
            const float* wr = WTs + (size_t)(k4+kk)*ldw + n0;
            ulonglong2 wA = *reinterpret_cast<const ulonglong2*>(wr);
            ulonglong2 wB = *reinterpret_cast<const ulonglong2*>(wr + 4);
            #pragma unroll
            for (int j = 0; j < 4; j++){
                unsigned long long x2 = pack2(reinterpret_cast<const float*>(&xv[j])[kk]);
                fma2(acc[0][j], x2, wA.x);
                fma2(acc[1][j], x2, wA.y);
                fma2(acc[2][j], x2, wB.x);
                fma2(acc[3][j], x2, wB.y);
            }
        }
    }
    #pragma unroll
    for (int j = 0; j < 4; j++){
        float* pr = P + (size_t)(r0+j)*ldo + n0;
        #pragma unroll
        for (int c = 0; c < 4; c++)
            *reinterpret_cast<float2*>(pr + 2*c) = *reinterpret_cast<float2*>(&acc[c][j]);
    }
}

// ---------------- phases ----------------
__device__ __forceinline__ void phase_lstm_gemm(int l, const float* xin, const float* hin,
                                                int wu0, int lane){
    for (int wu = wu0; wu < 1024; wu += GW){
        int u  = wu*32 + lane;
        int cg = u & 255;
        int bg = (u >> 8) & 7;
        int s  = u >> 11;                 // 0..15
        const float* X  = (s < 8) ? xin : hin;
        const float* WT = (s < 8) ? &g_WihT[l][0][0] : &g_WhhT[l][0][0];
        int koff = (s & 7) * 64;
        gemm_unit(X, koff, WT + (size_t)koff*(4*HID), 64, 4*HID,
                  &g_Pg[s][0][0], 4*HID, cg*8, bg*4);
    }
}

__device__ __forceinline__ void phase_lstm_act(int l, const float* bih, const float* bhh,
                                               int wu0, int lane){
    for (int wu = wu0; wu < 512; wu += GW){
        int e = wu*32 + lane;
        int b = e >> 9, j = e & 511;
        int bo = l * 4 * HID;
        float gi = bih[bo + j]         + bhh[bo + j];
        float gf = bih[bo + HID + j]   + bhh[bo + HID + j];
        float gg = bih[bo + 2*HID + j] + bhh[bo + 2*HID + j];
        float go = bih[bo + 3*HID + j] + bhh[bo + 3*HID + j];
        #pragma unroll
        for (int s = 0; s < 16; s++){
            const float* p = &g_Pg[s][b][0];
            gi += p[j]; gf += p[HID + j]; gg += p[2*HID + j]; go += p[3*HID + j];
        }
        int idx = (l * BATCH + b) * HID + j;
        float cold = g_c[idx];
        float si = 1.f / (1.f + expf(-gi));
        float sf = 1.f / (1.f + expf(-gf));
        float so = 1.f / (1.f + expf(-go));
        float c2 = sf * cold + si * tanhf(gg);
        g_c[idx] = c2;
        g_h[idx] = so * tanhf(c2);
    }
}

__device__ __forceinline__ void phase_proj_q(const float* X, int withQ, int wu0, int lane){
    for (int wu = wu0; wu < 1076; wu += GW){
        if (wu < 948){
            int u  = wu*32 + lane;
            int cg = u % 1264;
            int bg = (u / 1264) & 7;
            int s  = u / 10112;           // 0..2, KC = 172,172,168
            int koff = s * 172;
            int KC = (s == 2) ? 168 : 172;
            gemm_unit(X, koff, &g_projWT[0][0] + (size_t)koff*VPAD, KC, VPAD,
                      &g_Pp[s][0][0], VPAD, cg*8, bg*4);
        } else if (withQ){
            int qa = (wu - 948)*32 + lane;    // 4096 units
            int cg = qa & 63;
            int rg = (qa >> 6) & 15;
            int s  = qa >> 10;                // 0..3, KC=128
            gemm_unit(g_h, s*128, &g_WqT[0][0] + (size_t)(s*128)*HID, 128, HID,
                      &g_Pq[s][0][0], HID, cg*8, rg*4);
        }
    }
}

__device__ __forceinline__ void attention_warp(int aw, const float* bq, int lane){
    int lb = aw & 63, half = aw >> 6;
    int b = lb & 31;
    float qv[16];
    #pragma unroll
    for (int i = 0; i < 16; i++){
        int j = i*32 + lane;
        float a = bq[j];
        #pragma unroll
        for (int s = 0; s < 4; s++) a += g_Pq[s][lb][j];
        qv[i] = tanhf(a);
    }
    float scA = 0.f, scB = -INFINITY;
    for (int s = 0; s < SPOS; s++){
        const float* kp = &g_keys[b][s][0];
        float d = 0.f;
        #pragma unroll
        for (int i = 0; i < 16; i++) d += qv[i] * __ldg(kp + i*32 + lane);
        #pragma unroll
        for (int o = 16; o > 0; o >>= 1) d += __shfl_xor_sync(0xffffffffu, d, o);
        d *= (1.f / 7.f);
        if (lane == s)      scA = d;
        if (lane + 32 == s) scB = d;
    }
    float m = fmaxf(scA, scB);
    #pragma unroll
    for (int o = 16; o > 0; o >>= 1) m = fmaxf(m, __shfl_xor_sync(0xffffffffu, m, o));
    float eA = expf(scA - m);
    float eB = (lane + 32 < SPOS) ? expf(scB - m) : 0.f;
    float ssum = eA + eB;
    #pragma unroll
    for (int o = 16; o > 0; o >>= 1) ssum += __shfl_xor_sync(0xffffffffu, ssum, o);
    float inv = 1.f / ssum;
    float wA = eA * inv, wB = eB * inv;
    float av[8];
    #pragma unroll
    for (int i = 0; i < 8; i++) av[i] = 0.f;
    for (int s = 0; s < SPOS; s++){
        float w = (s < 32) ? __shfl_sync(0xffffffffu, wA, s)
                           : __shfl_sync(0xffffffffu, wB, s - 32);
        const float* vp = &g_vals[b][s][0];
        #pragma unroll
        for (int i = 0; i < 8; i++) av[i] += w * __ldg(vp + (half*8 + i)*32 + lane);
    }
    #pragma unroll
    for (int i = 0; i < 8; i++)
        g_attn[lb*HID + (half*8 + i)*32 + lane] = av[i];
}

__device__ __forceinline__ void phase_logits_attn(int tslot, int withAttn,
        const float* projb, const float* bq, int wu0, int lane){
    for (int wu = wu0; wu < GW; wu += GW){
        if (wu < 1056){
            int b = wu / 33, ch = wu % 33;
            int vend = ch*304 + 304; if (vend > VOC) vend = VOC;
            float best = -INFINITY; int bi = 0;
            for (int v = ch*304 + lane; v < vend; v += 32){
                float val = projb[v] + g_Pp[0][b][v] + g_Pp[1][b][v] + g_Pp[2][b][v];
                g_tmp[tslot][b][v] = val;
                if (val > best){ best = val; bi = v; }   // v increasing -> first-max kept
            }
            #pragma unroll
            for (int o = 16; o > 0; o >>= 1){
                float ov = __shfl_xor_sync(0xffffffffu, best, o);
                int   oi = __shfl_xor_sync(0xffffffffu, bi, o);
                if (ov > best || (ov == best && oi < bi)){ best = ov; bi = oi; }
            }
            if (lane == 0){ g_amv[b][ch] = best; g_ami[b][ch] = bi; }
        } else if (withAttn){
            attention_warp(wu - 1056, bq, lane);
        }
    }
}

__device__ __forceinline__ void phase_argmax_hatt(const float* embed, int wu0, int lane){
    for (int wu = wu0; wu < 544; wu += GW){
        if (wu < 32){
            int b = wu;
            float best = g_amv[b][0]; int bi = g_ami[b][0];
            for (int ch = 1; ch < 33; ch++){
                float v = g_amv[b][ch]; int i = g_ami[b][ch];
                if (v > best || (v == best && i < bi)){ best = v; bi = i; }
            }
            #pragma unroll
            for (int i = 0; i < 16; i++)
                g_emb[b*HID + i*32 + lane] = __ldg(&embed[(size_t)bi*HID + i*32 + lane]);
        } else {
            int u  = (wu - 32)*32 + lane;       // 16384 units
            int cg = u & 63;
            int rg = (u >> 6) & 15;
            int s  = u >> 10;                   // 0..15, KC=64
            const float* X = (s < 8) ? g_attn : g_h;
            int krow = (s < 8) ? s*64 : HID + (s - 8)*64;
            int koff = (s & 7) * 64;
            gemm_unit(X, koff, &g_hattWT[krow][0], 64, HID,
                      &g_Ph[s][0][0], HID, cg*8, rg*4);
        }
    }
}

__device__ __forceinline__ void phase_hatt_act(const float* hattb, int wu0, int lane){
    for (int wu = wu0; wu < 1024; wu += GW){
        int e = wu*32 + lane;
        int lb = e >> 9, j = e & 511;
        float a = hattb[j];
        #pragma unroll
        for (int s = 0; s < 16; s++) a += g_Ph[s][lb][j];
        g_h[lb*HID + j] = tanhf(a);
    }
}

__device__ __forceinline__ void phase_out(float* out, int wu0, int lane){
    for (int wu = wu0; wu < 10000; wu += GW){
        int e = wu*32 + lane;           // < 320000
        int b = e / VOC, v = e % VOC;
        float r[TMAX];
        #pragma unroll
        for (int t = 0; t < TMAX; t++) r[t] = g_tmp[t][b][v];
        float4* o4 = reinterpret_cast<float4*>(out + ((size_t)b*VOC + v)*TMAX);
        #pragma unroll
        for (int i = 0; i < 5; i++) o4[i] = reinterpret_cast<float4*>(r)[i];
    }
}

// ---------------- the persistent decoder kernel ----------------
__global__ __launch_bounds__(NT, 1)
void decoder_persistent(const float* __restrict__ bq, const float* __restrict__ bih,
                        const float* __restrict__ bhh, const float* __restrict__ projb,
                        const float* __restrict__ hattb, const float* __restrict__ embed,
                        float* __restrict__ out){
    int tid = threadIdx.x, blk = blockIdx.x;
    int wl = tid >> 5, lane = tid & 31;
    int wu0 = wl * NB + blk;

    // prologue: t=0 output slice from emb0 (no argmax, no attention)
    phase_proj_q(g_emb, 0, wu0, lane);
    gridbar();
    phase_logits_attn(0, 0, projb, bq, wu0, lane);
    gridbar();

    float* h0 = g_h;
    float* h1 = g_h + BATCH*HID;

    for (int t = 0; t < TMAX - 1; t++){
        phase_lstm_gemm(0, g_emb, h0, wu0, lane);
        gridbar();
        phase_lstm_act(0, bih, bhh, wu0, lane);
        gridbar();
        phase_lstm_gemm(1, h0, h1, wu0, lane);
        gridbar();
        phase_lstm_act(1, bih, bhh, wu0, lane);
        gridbar();
        phase_proj_q(h1, 1, wu0, lane);
        gridbar();
        phase_logits_attn(t + 1, 1, projb, bq, wu0, lane);
        gridbar();
        phase_argmax_hatt(embed, wu0, lane);
        gridbar();
        phase_hatt_act(hattb, wu0, lane);
        gridbar();
    }
    phase_out(out, wu0, lane);
}

// ---------------- setup kernels ----------------
__global__ void transpose_pad(const float* __restrict__ W, float* __restrict__ WT,
                              int N, int K, int Npad){
    __shared__ float t[32][33];
    int n0 = blockIdx.x * 32, k0 = blockIdx.y * 32;
    int tx = threadIdx.x, ty = threadIdx.y;
    int n = n0 + ty, k = k0 + tx;
    float v = 0.f;
    if (n < N && k < K) v = W[(size_t)n * K + k];
    t[ty][tx] = v;
    __syncthreads();
    int kk = k0 + ty, nn = n0 + tx;
    if (kk < K && nn < Npad) WT[(size_t)kk * Npad + nn] = t[tx][ty];
}

__global__ void precompute_kv(const float* __restrict__ img, const float* __restrict__ Wk,
                              const float* __restrict__ bk, const float* __restrict__ Wv,
                              const float* __restrict__ bv){
    __shared__ float wk_s[SPOS][SPOS], wv_s[SPOS][SPOS];
    __shared__ float bk_s[SPOS], bv_s[SPOS];
    int tid = threadIdx.x;
    for (int i = tid; i < SPOS*SPOS; i += 128){ wk_s[i/SPOS][i%SPOS] = Wk[i]; wv_s[i/SPOS][i%SPOS] = Wv[i]; }
    if (tid < SPOS){ bk_s[tid] = bk[tid]; bv_s[tid] = bv[tid]; }
    __syncthreads();
    int b = blockIdx.x;
    int d = blockIdx.y * 128 + tid;
    float ch[SPOS];
    const float* cp = img + ((size_t)b * HID + d) * SPOS;
    #pragma unroll
    for (int s = 0; s < SPOS; s++) ch[s] = cp[s];
    for (int s = 0; s < SPOS; s++){
        float ak = bk_s[s], av = bv_s[s];
        #pragma unroll
        for (int sp = 0; sp < SPOS; sp++){ ak += ch[sp] * wk_s[s][sp]; av += ch[sp] * wv_s[s][sp]; }
        g_keys[b][s][d] = tanhf(ak);
        g_vals[b][s][d] = tanhf(av);
    }
}

__global__ void init_state(const float* __restrict__ pooled, const float* __restrict__ embed,
                           const int* __restrict__ sos){
    int idx = blockIdx.x * blockDim.x + threadIdx.x;
    if (idx < L2L * BATCH * HID){
        float p = pooled[idx % (BATCH * HID)];
        g_h[idx] = p; g_c[idx] = p;
    }
    if (idx < BATCH * HID){
        g_emb[idx] = embed[(size_t)(*sos) * HID + (idx % HID)];
    }
}

// ---------------- host ----------------
static float* symaddr(const void* sym){
    void* p = nullptr;
    cudaGetSymbolAddress(&p, sym);
    return (float*)p;
}

extern "C" void kernel_launch(void* const* d_in, const int* in_sizes, int n_in,
                              void* d_out, int out_size){
    const float* img    = (const float*)d_in[0];
    const float* pooled = (const float*)d_in[1];
    const float* embed  = (const float*)d_in[2];
    const float* Wq     = (const float*)d_in[3];
    const float* bq     = (const float*)d_in[4];
    const float* Wk     = (const float*)d_in[5];
    const float* bk     = (const float*)d_in[6];
    const float* Wv     = (const float*)d_in[7];
    const float* bv     = (const float*)d_in[8];
    const float* Wih    = (const float*)d_in[9];
    const float* Whh    = (const float*)d_in[10];
    const float* bih    = (const float*)d_in[11];
    const float* bhh    = (const float*)d_in[12];
    const float* projW  = (const float*)d_in[13];
    const float* projb  = (const float*)d_in[14];
    const float* hattW  = (const float*)d_in[15];
    const float* hattb  = (const float*)d_in[16];
    const int*   sos    = (const int*)d_in[17];

    float* WihT   = symaddr(g_WihT);
    float* WhhT   = symaddr(g_WhhT);
    float* WqT    = symaddr(g_WqT);
    float* hattWT = symaddr(g_hattWT);
    float* projWT = symaddr(g_projWT);

    dim3 tb(32, 32);
    transpose_pad<<<dim3(16, 16), tb>>>(Wq,    WqT,    HID,  HID,   HID);
    transpose_pad<<<dim3(16, 32), tb>>>(hattW, hattWT, HID,  2*HID, HID);
    transpose_pad<<<dim3(316,16), tb>>>(projW, projWT, VOC,  HID,   VPAD);  // 316*32 = 10112 = VPAD
    for (int l = 0; l < L2L; l++){
        transpose_pad<<<dim3(64, 16), tb>>>(Wih + (size_t)l*4*HID*HID, WihT + (size_t)l*HID*4*HID, 4*HID, HID, 4*HID);
        transpose_pad<<<dim3(64, 16), tb>>>(Whh + (size_t)l*4*HID*HID, WhhT + (size_t)l*HID*4*HID, 4*HID, HID, 4*HID);
    }
    precompute_kv<<<dim3(BATCH, 4), 128>>>(img, Wk, bk, Wv, bv);
    init_state<<<128, 256>>>(pooled, embed, sos);

    decoder_persistent<<<NB, NT>>>(bq, bih, bhh, projb, hattb, embed, (float*)d_out);
}